// round 6
// baseline (speedup 1.0000x reference)
#include <cuda_runtime.h>
#include <cuda_fp16.h>
#include <math.h>
#include <stdint.h>

// ---------------- problem constants ----------------
#define PP   25
#define QQ   2000
#define CC   640
#define SS   25
#define TILE 16000          // CC*SS

#define MPAD 640            // Gram rows padded (625 valid)
#define NKC  40             // K chunks of 16
#define CHUNK_BYTES (MPAD * 32)   // 20480 B
#define NRING 3
#define BQ_BYTES 41472      // 32 rows x 648 halves x 2B

// output layout: [ftrain_out 400000][ftest_out 32000000][am 50000][cls 10000]
#define OFT_TE  400000
#define OFT_AM  32400000
#define OFT_CLS 32450000

// ---------------- device scratch ----------------
__device__ __align__(16) unsigned char g_Ah[NKC * CHUNK_BYTES];      // swizzled fp16 A image
__device__ __align__(16) unsigned char g_Bh[(size_t)QQ * BQ_BYTES];  // per-q fp16 B operand image
__device__ float g_att1[PP * QQ * SS];                               // att1[p][q][xy]

// ---------------- smem byte offsets (cam_main) ----------------
#define OB_A     0                        // ring: 3 x 20480 = 61440
#define OB_B     61440                    // 2 x 41472 = 82944 -> 144384
#define OB_GH    144384                   // 2 x fp16 G (625 x stride26) = 2 x 32512
#define GH_STRIDE_Q 32512
#define OB_ATT   209408                   // 2 x 625 fp32 = 5000
#define OB_KN    214408                   // 16 x 112 x 4 = 7168
#define OB_W1F   221576                   // 125 f
#define OB_W2    222076                   // 125 f
#define OB_B1F   222576                   // 5 f
#define OB_B2S   222596                   // 25 f
#define OB_TS    222696                   // 2 x 25 f
#define SMEM_BYTES 222896

#define ATI  (OB_ATT/4)
#define KNI  (OB_KN/4)

__device__ __forceinline__ float warp_sum(float v) {
    #pragma unroll
    for (int o = 16; o; o >>= 1) v += __shfl_xor_sync(0xffffffffu, v, o);
    return v;
}
__device__ __forceinline__ void cp_async16(uint32_t smem_addr, const void* gptr) {
    asm volatile("cp.async.cg.shared.global [%0], [%1], 16;" :: "r"(smem_addr), "l"(gptr));
}
#define CP_COMMIT() asm volatile("cp.async.commit_group;")
#define CP_WAIT1()  asm volatile("cp.async.wait_group 1;" ::: "memory")

__device__ __forceinline__ void ldsm_x4(uint32_t& r0, uint32_t& r1, uint32_t& r2, uint32_t& r3,
                                        uint32_t addr) {
    asm volatile("ldmatrix.sync.aligned.m8n8.x4.shared.b16 {%0,%1,%2,%3}, [%4];"
                 : "=r"(r0), "=r"(r1), "=r"(r2), "=r"(r3) : "r"(addr));
}
__device__ __forceinline__ void mma16816(float& d0, float& d1, float& d2, float& d3,
                                         uint32_t a0, uint32_t a1, uint32_t a2, uint32_t a3,
                                         uint32_t b0, uint32_t b1) {
    asm volatile("mma.sync.aligned.m16n8k16.row.col.f32.f16.f16.f32 "
                 "{%0,%1,%2,%3}, {%4,%5,%6,%7}, {%8,%9}, {%0,%1,%2,%3};"
                 : "+f"(d0), "+f"(d1), "+f"(d2), "+f"(d3)
                 : "r"(a0), "r"(a1), "r"(a2), "r"(a3), "r"(b0), "r"(b1));
}

// ---------------- K1: build swizzled fp16 A image ----------------
__global__ void __launch_bounds__(256) cam_prep_A(const float* __restrict__ ftrain) {
    extern __shared__ float sm[];
    float* xs    = sm;                       // 16000 f
    float* inv_s = sm + 16000;               // 25 f
    unsigned char* buf = (unsigned char*)sm + 64128;  // 32000 B
    int p = blockIdx.x, tid = threadIdx.x, lane = tid & 31, w = tid >> 5;
    const float4* fp4 = (const float4*)(ftrain + p * TILE);
    float4* xs4 = (float4*)xs;
    for (int i = tid; i < 4000; i += 256) xs4[i] = fp4[i];
    __syncthreads();
    for (int s = w; s < SS; s += 8) {
        float acc = 0.f;
        #pragma unroll
        for (int k = 0; k < 20; k++) { float v = xs[(lane + 32 * k) * SS + s]; acc += v * v; }
        acc = warp_sum(acc);
        if (lane == 0) inv_s[s] = 1.f / fmaxf(sqrtf(acc), 1e-12f);
    }
    __syncthreads();
    for (int idx = tid; idx < TILE; idx += 256) {
        int c = idx / SS, s = idx - c * SS;
        __half v = __float2half_rn(xs[idx] * inv_s[s]);
        int m = p * SS + s;
        int kc = c >> 4, k = c & 15;
        uint32_t off = (uint32_t)((((k >> 3) ^ ((m >> 2) & 1)) << 4) + ((k & 7) << 1));
        *(__half*)(buf + kc * 800 + s * 32 + off) = v;
    }
    __syncthreads();
    for (int i = tid; i < 2000; i += 256) {
        int kc = i / 50, j = i - kc * 50;
        *(float4*)(g_Ah + (size_t)(kc * MPAD + p * SS) * 32 + j * 16) =
            *(const float4*)(buf + kc * 800 + j * 16);
    }
}

// ---------------- K1b: build per-q fp16 B operand image ----------------
// layout per q (matches main's smem B): half index (s*648 + c), rows 25..31 zero,
// cols 640..647 zero.
__global__ void __launch_bounds__(256) cam_prep_B(const float* __restrict__ ftest) {
    extern __shared__ float sm[];
    float* xs    = sm;          // 16000 f
    float* inv_s = sm + 16000;  // 25 f
    int q = blockIdx.x, tid = threadIdx.x, lane = tid & 31, w = tid >> 5;
    const float4* fq4 = (const float4*)(ftest + (size_t)q * TILE);
    float4* xs4 = (float4*)xs;
    for (int i = tid; i < 4000; i += 256) xs4[i] = fq4[i];
    __syncthreads();
    for (int s = w; s < SS; s += 8) {
        float acc = 0.f;
        #pragma unroll
        for (int k = 0; k < 20; k++) { float v = xs[(lane + 32 * k) * SS + s]; acc += v * v; }
        acc = warp_sum(acc);
        if (lane == 0) inv_s[s] = 1.f / fmaxf(sqrtf(acc), 1e-12f);
    }
    __syncthreads();
    unsigned char* dst = g_Bh + (size_t)q * BQ_BYTES;
    // data rows: 25 x 320 half2 (coalesced 4B writes)
    for (int i = tid; i < 8000; i += 256) {
        int s = i / 320, c2 = i - s * 320;
        float iv = inv_s[s];
        __half2 v = __floats2half2_rn(xs[(2 * c2) * SS + s] * iv,
                                      (2 * c2 + 1 < CC ? xs[(2 * c2 + 1) * SS + s] * iv : 0.f));
        *(__half2*)(dst + (s * 648 + 2 * c2) * 2) = v;
    }
    // zero pad rows 25..31 (7 x 324 uint)
    for (int i = tid; i < 2268; i += 256) {
        int n = 25 + i / 324, j = i - (n - 25) * 324;
        *(uint32_t*)(dst + n * 1296 + j * 4) = 0u;
    }
    // zero col tails 640..647 for data rows (25 x 4 uint)
    for (int i = tid; i < 100; i += 256) {
        int s = i / 4, j = i - s * 4;
        *(uint32_t*)(dst + (s * 648 + 640 + 2 * j) * 2) = 0u;
    }
}

// ---------------- K2: main kernel, 2 q per CTA ----------------
__global__ void __launch_bounds__(512, 1) cam_main(
    const float* __restrict__ ftest,
    const float* __restrict__ conv1_w, const float* __restrict__ conv1_b,
    const float* __restrict__ bn_gamma, const float* __restrict__ bn_beta,
    const float* __restrict__ bn_mean, const float* __restrict__ bn_var,
    const float* __restrict__ conv2_w, const float* __restrict__ conv2_b,
    float* __restrict__ out)
{
    extern __shared__ char smraw[];
    float* smf = (float*)smraw;
    const int tid = threadIdx.x, lane = tid & 31, w = tid >> 5;
    const int h = w >> 3;                 // q index within CTA
    const int wl = w & 7;
    const int q0 = blockIdx.x * 2;
    const uint32_t smb = (uint32_t)__cvta_generic_to_shared(smraw);

    // group 1: both B images
    for (int j = tid; j < (2 * BQ_BYTES) / 16; j += 512)
        cp_async16(smb + OB_B + j * 16, g_Bh + (size_t)q0 * BQ_BYTES + j * 16);
    CP_COMMIT();
    // groups 2,3: A chunks 0,1
    #pragma unroll
    for (int pc = 0; pc < 2; pc++) {
        for (int j = tid; j < CHUNK_BYTES / 16; j += 512)
            cp_async16(smb + OB_A + pc * CHUNK_BYTES + j * 16,
                       g_Ah + (size_t)pc * CHUNK_BYTES + j * 16);
        CP_COMMIT();
    }

    // small weights (BN folded into conv1)
    for (int i = tid; i < 125; i += 512) {
        int cc = i / 25;
        smf[OB_W1F/4 + i] = conv1_w[i] * bn_gamma[cc] * rsqrtf(bn_var[cc] + 1e-5f);
        smf[OB_W2/4 + i]  = conv2_w[i];
    }
    if (tid < 5) {
        float scv = bn_gamma[tid] * rsqrtf(bn_var[tid] + 1e-5f);
        smf[OB_B1F/4 + tid] = (conv1_b[tid] - bn_mean[tid]) * scv + bn_beta[tid];
    }
    if (tid < 25) smf[OB_B2S/4 + tid] = conv2_b[tid];

    // ---- GEMM: each warp 5 m-tiles x 4 n-tiles for its q ----
    float acc[5][4][4];
    #pragma unroll
    for (int t = 0; t < 5; t++)
        #pragma unroll
        for (int n = 0; n < 4; n++)
            #pragma unroll
            for (int e = 0; e < 4; e++) acc[t][n][e] = 0.f;

    const int nrow = lane >> 2;
    const int kq   = lane & 3;
    const uint32_t bqbase = OB_B + h * BQ_BYTES;

    for (int i = 0; i < NKC; i++) {
        CP_WAIT1();              // with always-commit below, chunk i is provably resident
        __syncthreads();
        if (i + 2 < NKC) {
            int b = (i + 2) % NRING;
            for (int j = tid; j < CHUNK_BYTES / 16; j += 512)
                cp_async16(smb + OB_A + b * CHUNK_BYTES + j * 16,
                           g_Ah + (size_t)(i + 2) * CHUNK_BYTES + j * 16);
        }
        CP_COMMIT();             // commit every iteration (possibly empty group)
        const uint32_t abase = smb + OB_A + (i % NRING) * CHUNK_BYTES;

        uint32_t bf[4][2];
        #pragma unroll
        for (int nt = 0; nt < 4; nt++) {
            int n = nt * 8 + nrow;
            uint32_t bidx = bqbase + (uint32_t)(n * 648 + i * 16 + kq * 2) * 2;
            bf[nt][0] = *(const uint32_t*)(smraw + bidx);
            bf[nt][1] = *(const uint32_t*)(smraw + bidx + 16);
        }

        #pragma unroll
        for (int j = 0; j < 5; j++) {
            int mt = wl + 8 * j;
            int m = mt * 16 + (lane & 15);
            uint32_t addr = abase + m * 32 + ((((lane >> 4) ^ (m >> 2)) & 1) << 4);
            uint32_t a0, a1, a2, a3;
            ldsm_x4(a0, a1, a2, a3, addr);
            #pragma unroll
            for (int nt = 0; nt < 4; nt++)
                mma16816(acc[j][nt][0], acc[j][nt][1], acc[j][nt][2], acc[j][nt][3],
                         a0, a1, a2, a3, bf[nt][0], bf[nt][1]);
        }
    }

    // ---- store G (fp16, per-q buffer): all 16 warps in parallel ----
    {
        __half* gh = (__half*)(smraw + OB_GH + h * GH_STRIDE_Q);
        #pragma unroll
        for (int j = 0; j < 5; j++) {
            int mt = wl + 8 * j;
            int r0 = mt * 16 + (lane >> 2);
            int r1 = r0 + 8;
            #pragma unroll
            for (int nt = 0; nt < 4; nt++) {
                int c = nt * 8 + (lane & 3) * 2;
                if (c + 1 < 25) {
                    if (r0 < 625)
                        *(__half2*)(gh + r0 * 26 + c) = __floats2half2_rn(acc[j][nt][0], acc[j][nt][1]);
                    if (r1 < 625)
                        *(__half2*)(gh + r1 * 26 + c) = __floats2half2_rn(acc[j][nt][2], acc[j][nt][3]);
                } else if (c < 25) {
                    if (r0 < 625) gh[r0 * 26 + c] = __float2half_rn(acc[j][nt][0]);
                    if (r1 < 625) gh[r1 * 26 + c] = __float2half_rn(acc[j][nt][2]);
                }
            }
        }
    }
    __syncthreads();

    // ---- per-p epilogue: halves fully parallel (warps 0-7: q0, 8-15: q1) ----
    const int q = q0 + h;
    const __half* gh = (const __half*)(smraw + OB_GH + h * GH_STRIDE_Q);
    for (int p = wl; p < PP; p += 8) {
        float* kn = smf + KNI + w * 112;
        if (lane < 25) {
            float a1 = 0.f, a2 = 0.f;
            int rowb = (p * 25 + lane) * 26;
            int colb = p * 25 * 26 + lane;
            #pragma unroll
            for (int j = 0; j < 25; j++) {
                a1 += __half2float(gh[rowb + j]);
                a2 += __half2float(gh[colb + j * 26]);
            }
            kn[lane]      = a1 * (1.f / 25.f);   // g1
            kn[25 + lane] = a2 * (1.f / 25.f);   // g2
        }
        __syncwarp();
        if (lane < 5) {
            float a = smf[OB_B1F/4 + lane];
            #pragma unroll
            for (int j = 0; j < 25; j++) a += kn[j] * smf[OB_W1F/4 + lane * 25 + j];
            kn[50 + lane] = fmaxf(a, 0.f);
        } else if (lane >= 8 && lane < 13) {
            int ii = lane - 8;
            float a = smf[OB_B1F/4 + ii];
            #pragma unroll
            for (int j = 0; j < 25; j++) a += kn[25 + j] * smf[OB_W1F/4 + ii * 25 + j];
            kn[55 + ii] = fmaxf(a, 0.f);
        }
        __syncwarp();
        if (lane < 25) {
            float a1 = smf[OB_B2S/4 + lane], a2 = a1;
            #pragma unroll
            for (int ii = 0; ii < 5; ii++) {
                float wv = smf[OB_W2/4 + lane * 5 + ii];
                a1 += kn[50 + ii] * wv;
                a2 += kn[55 + ii] * wv;
            }
            kn[60 + lane] = fmaxf(a1, 0.f);  // k1
            kn[85 + lane] = fmaxf(a2, 0.f);  // k2
        }
        __syncwarp();
        if (lane < 25) {
            float att1 = 0.f, attt = 0.f;
            int colb = p * 25 * 26 + lane;
            int rowb = (p * 25 + lane) * 26;
            #pragma unroll
            for (int j = 0; j < 25; j++) {
                att1 += kn[60 + j] * __half2float(gh[colb + j * 26]);
                attt += __half2float(gh[rowb + j]) * kn[85 + j];
            }
            g_att1[(size_t)(p * QQ + q) * SS + lane] = att1;
            smf[ATI + h * 625 + p * 25 + lane] = attt;
        }
    }
    asm volatile("bar.sync %0, 256;" :: "r"(h + 1) : "memory");

    // am softmax (warp h*8) + cls softmax (warp h*8+1)
    if (wl == 0) {
        float val = 0.f;
        if (lane < 25) {
            #pragma unroll
            for (int j = 0; j < 25; j++) val += smf[ATI + h * 625 + j * 25 + lane];
            val *= (1.f / 25.f);
        }
        float m = (lane < 25) ? val : -1e30f;
        #pragma unroll
        for (int o = 16; o; o >>= 1) m = fmaxf(m, __shfl_xor_sync(0xffffffffu, m, o));
        float e = (lane < 25) ? expf(val - m) : 0.f;
        float ssum = e;
        #pragma unroll
        for (int o = 16; o; o >>= 1) ssum += __shfl_xor_sync(0xffffffffu, ssum, o);
        float a = e / ssum;
        if (lane < 25) {
            out[OFT_AM + q * SS + lane] = a;
            smf[OB_TS/4 + h * 25 + lane] = a + 1.f;
        }
    } else if (wl == 1) {
        float rs = 0.f;
        if (lane < 25) {
            #pragma unroll
            for (int j = 0; j < 25; j++) rs += smf[ATI + h * 625 + lane * 25 + j];
        }
        int g = (lane < 5) ? lane : 4;
        float cg = 0.f;
        #pragma unroll
        for (int i = 0; i < 5; i++) cg += __shfl_sync(0xffffffffu, rs, g * 5 + i);
        cg *= (1.f / 125.f);
        float m = (lane < 5) ? cg : -1e30f;
        #pragma unroll
        for (int o = 4; o; o >>= 1) m = fmaxf(m, __shfl_xor_sync(0xffffffffu, m, o));
        float e = (lane < 5) ? expf(cg - m) : 0.f;
        float ssum = e;
        #pragma unroll
        for (int o = 4; o; o >>= 1) ssum += __shfl_xor_sync(0xffffffffu, ssum, o);
        if (lane < 5) out[OFT_CLS + q * 5 + lane] = e / ssum;
    }
    asm volatile("bar.sync %0, 256;" :: "r"(h + 1) : "memory");

    // ftest_out = raw ftest * (am + 1), each half writes its q
    {
        const int t2 = tid & 255;
        const float4* fq4 = (const float4*)(ftest + (size_t)q * TILE);
        float4* outq = (float4*)(out + OFT_TE + (size_t)q * TILE);
        for (int i = t2; i < 4000; i += 256) {
            float4 b = fq4[i];
            int s = (i * 4) % 25;
            float4 o;
            o.x = b.x * smf[OB_TS/4 + h * 25 + s]; s = (s == 24) ? 0 : s + 1;
            o.y = b.y * smf[OB_TS/4 + h * 25 + s]; s = (s == 24) ? 0 : s + 1;
            o.z = b.z * smf[OB_TS/4 + h * 25 + s]; s = (s == 24) ? 0 : s + 1;
            o.w = b.w * smf[OB_TS/4 + h * 25 + s];
            outq[i] = o;
        }
    }
}

// ---------------- K3: reduce att1 over q, softmax, ftrain_out ----------------
__global__ void __launch_bounds__(256) cam_final_train(const float* __restrict__ ftrain,
                                                       float* __restrict__ out) {
    extern __shared__ float bins[];       // 256*25 floats
    __shared__ float att_s[SS];
    int p = blockIdx.x, tid = threadIdx.x, lane = tid & 31, w = tid >> 5;
    for (int i = 0; i < 25; i++) bins[tid * 25 + i] = 0.f;
    __syncthreads();
    const float4* a4 = (const float4*)(g_att1 + (size_t)p * QQ * SS);
    for (int jj = tid; jj < 12500; jj += 256) {
        float4 v = a4[jj];
        int s = (jj * 4) % 25;
        bins[tid * 25 + s] += v.x; s = (s == 24) ? 0 : s + 1;
        bins[tid * 25 + s] += v.y; s = (s == 24) ? 0 : s + 1;
        bins[tid * 25 + s] += v.z; s = (s == 24) ? 0 : s + 1;
        bins[tid * 25 + s] += v.w;
    }
    __syncthreads();
    for (int s = w; s < 25; s += 8) {
        float acc = 0.f;
        #pragma unroll
        for (int t = 0; t < 8; t++) acc += bins[(lane + 32 * t) * 25 + s];
        acc = warp_sum(acc);
        if (lane == 0) att_s[s] = acc * (1.f / (float)QQ);
    }
    __syncthreads();
    if (w == 0) {
        float val = (lane < 25) ? att_s[lane] : -1e30f;
        float m = val;
        #pragma unroll
        for (int o = 16; o; o >>= 1) m = fmaxf(m, __shfl_xor_sync(0xffffffffu, m, o));
        float e = (lane < 25) ? expf(val - m) : 0.f;
        float ssum = e;
        #pragma unroll
        for (int o = 16; o; o >>= 1) ssum += __shfl_xor_sync(0xffffffffu, ssum, o);
        if (lane < 25) att_s[lane] = e / ssum + 1.f;
    }
    __syncthreads();
    const float4* fp4 = (const float4*)(ftrain + p * TILE);
    float4* outp = (float4*)(out + (size_t)p * TILE);
    for (int i = tid; i < 4000; i += 256) {
        float4 b = fp4[i];
        int s = (i * 4) % 25;
        float4 o;
        o.x = b.x * att_s[s]; s = (s == 24) ? 0 : s + 1;
        o.y = b.y * att_s[s]; s = (s == 24) ? 0 : s + 1;
        o.z = b.z * att_s[s]; s = (s == 24) ? 0 : s + 1;
        o.w = b.w * att_s[s];
        outp[i] = o;
    }
}

// ---------------- launch ----------------
extern "C" void kernel_launch(void* const* d_in, const int* in_sizes, int n_in,
                              void* d_out, int out_size) {
    const float* ftrain  = (const float*)d_in[0];
    const float* ftest   = (const float*)d_in[1];
    const float* conv1_w = (const float*)d_in[6];
    const float* conv1_b = (const float*)d_in[7];
    const float* bn_gamma= (const float*)d_in[8];
    const float* bn_beta = (const float*)d_in[9];
    const float* bn_mean = (const float*)d_in[10];
    const float* bn_var  = (const float*)d_in[11];
    const float* conv2_w = (const float*)d_in[12];
    const float* conv2_b = (const float*)d_in[13];
    float* out = (float*)d_out;

    const int prepA_smem = 64128 + 32000;
    const int prepB_smem = (16000 + 32) * 4;
    const int final_smem = 256 * 25 * 4;
    cudaFuncSetAttribute(cam_prep_A,      cudaFuncAttributeMaxDynamicSharedMemorySize, prepA_smem);
    cudaFuncSetAttribute(cam_prep_B,      cudaFuncAttributeMaxDynamicSharedMemorySize, prepB_smem);
    cudaFuncSetAttribute(cam_main,        cudaFuncAttributeMaxDynamicSharedMemorySize, SMEM_BYTES);
    cudaFuncSetAttribute(cam_final_train, cudaFuncAttributeMaxDynamicSharedMemorySize, final_smem);

    cam_prep_A<<<PP, 256, prepA_smem>>>(ftrain);
    cam_prep_B<<<QQ, 256, prepB_smem>>>(ftest);
    cam_main<<<QQ / 2, 512, SMEM_BYTES>>>(ftest, conv1_w, conv1_b, bn_gamma, bn_beta,
                                          bn_mean, bn_var, conv2_w, conv2_b, out);
    cam_final_train<<<PP, 256, final_smem>>>(ftrain, out);
}

// round 7
// speedup vs baseline: 1.2570x; 1.2570x over previous
#include <cuda_runtime.h>
#include <cuda_fp16.h>
#include <math.h>
#include <stdint.h>

// ---------------- problem constants ----------------
#define PP   25
#define QQ   2000
#define CC   640
#define SS   25
#define TILE 16000          // CC*SS

#define MPAD 640            // Gram rows padded (625 valid)
#define NKC  40             // K chunks of 16
#define CHUNK_BYTES (MPAD * 32)   // 20480 B
#define NRING 4
#define BQ_B  32400         // 25 rows x 648 halves x 2B (no pad rows)

// output layout: [ftrain_out 400000][ftest_out 32000000][am 50000][cls 10000]
#define OFT_TE  400000
#define OFT_AM  32400000
#define OFT_CLS 32450000

// ---------------- device scratch ----------------
__device__ __align__(16) unsigned char g_Ah[NKC * CHUNK_BYTES]; // swizzled fp16 A image
__device__ float g_att1[PP * QQ * SS];                          // att1[p][q][xy]
__device__ float g_part[200 * SS];                              // partial sums for final

// ---------------- smem byte offsets (cam_main) ----------------
#define OB_A     0                        // ring: 4 x 20480 = 81920
#define OB_B     81920                    // 2 x 32400 = 64800 -> 146720
#define OB_GH    146720                   // 2 x fp16 G (625 x stride26) ; also fq staging
#define GH_STRIDE_Q 32512
#define OB_ATT   211744                   // 2 x 625 fp32 = 5000
#define OB_KN    216744                   // 16 x 112 x 4 = 7168
#define OB_W1F   223912                   // 125 f
#define OB_W2    224412                   // 125 f
#define OB_B1F   224912                   // 5 f
#define OB_B2S   224932                   // 25 f
#define OB_NINV  225032                   // 2 x 25 f
#define OB_TS    225232                   // 2 x 25 f
#define SMEM_BYTES 225440

#define ATI  (OB_ATT/4)
#define KNI  (OB_KN/4)

__device__ __forceinline__ float warp_sum(float v) {
    #pragma unroll
    for (int o = 16; o; o >>= 1) v += __shfl_xor_sync(0xffffffffu, v, o);
    return v;
}
__device__ __forceinline__ void cp_async16(uint32_t smem_addr, const void* gptr) {
    asm volatile("cp.async.cg.shared.global [%0], [%1], 16;" :: "r"(smem_addr), "l"(gptr));
}
#define CP_COMMIT() asm volatile("cp.async.commit_group;")
#define CP_WAIT2()  asm volatile("cp.async.wait_group 2;" ::: "memory")

__device__ __forceinline__ void ldsm_x4(uint32_t& r0, uint32_t& r1, uint32_t& r2, uint32_t& r3,
                                        uint32_t addr) {
    asm volatile("ldmatrix.sync.aligned.m8n8.x4.shared.b16 {%0,%1,%2,%3}, [%4];"
                 : "=r"(r0), "=r"(r1), "=r"(r2), "=r"(r3) : "r"(addr));
}
__device__ __forceinline__ void mma16816(float& d0, float& d1, float& d2, float& d3,
                                         uint32_t a0, uint32_t a1, uint32_t a2, uint32_t a3,
                                         uint32_t b0, uint32_t b1) {
    asm volatile("mma.sync.aligned.m16n8k16.row.col.f32.f16.f16.f32 "
                 "{%0,%1,%2,%3}, {%4,%5,%6,%7}, {%8,%9}, {%0,%1,%2,%3};"
                 : "+f"(d0), "+f"(d1), "+f"(d2), "+f"(d3)
                 : "r"(a0), "r"(a1), "r"(a2), "r"(a3), "r"(b0), "r"(b1));
}

// ---------------- K1: build swizzled fp16 A image ----------------
__global__ void __launch_bounds__(256) cam_prep_A(const float* __restrict__ ftrain) {
    extern __shared__ float sm[];
    float* xs    = sm;                       // 16000 f
    float* inv_s = sm + 16000;               // 25 f
    unsigned char* buf = (unsigned char*)sm + 64128;  // 32000 B
    int p = blockIdx.x, tid = threadIdx.x, lane = tid & 31, w = tid >> 5;
    const float4* fp4 = (const float4*)(ftrain + p * TILE);
    float4* xs4 = (float4*)xs;
    for (int i = tid; i < 4000; i += 256) xs4[i] = fp4[i];
    __syncthreads();
    for (int s = w; s < SS; s += 8) {
        float acc = 0.f;
        #pragma unroll
        for (int k = 0; k < 20; k++) { float v = xs[(lane + 32 * k) * SS + s]; acc += v * v; }
        acc = warp_sum(acc);
        if (lane == 0) inv_s[s] = 1.f / fmaxf(sqrtf(acc), 1e-12f);
    }
    __syncthreads();
    for (int idx = tid; idx < TILE; idx += 256) {
        int c = idx / SS, s = idx - c * SS;
        __half v = __float2half_rn(xs[idx] * inv_s[s]);
        int m = p * SS + s;
        int kc = c >> 4, k = c & 15;
        uint32_t off = (uint32_t)((((k >> 3) ^ ((m >> 2) & 1)) << 4) + ((k & 7) << 1));
        *(__half*)(buf + kc * 800 + s * 32 + off) = v;
    }
    __syncthreads();
    for (int i = tid; i < 2000; i += 256) {
        int kc = i / 50, j = i - kc * 50;
        *(float4*)(g_Ah + (size_t)(kc * MPAD + p * SS) * 32 + j * 16) =
            *(const float4*)(buf + kc * 800 + j * 16);
    }
}

// ---------------- K2: main kernel, 2 q per CTA ----------------
__global__ void __launch_bounds__(512, 1) cam_main(
    const float* __restrict__ ftest,
    const float* __restrict__ conv1_w, const float* __restrict__ conv1_b,
    const float* __restrict__ bn_gamma, const float* __restrict__ bn_beta,
    const float* __restrict__ bn_mean, const float* __restrict__ bn_var,
    const float* __restrict__ conv2_w, const float* __restrict__ conv2_b,
    float* __restrict__ out)
{
    extern __shared__ char smraw[];
    float* smf = (float*)smraw;
    const int tid = threadIdx.x, lane = tid & 31, w = tid >> 5;
    const int h = w >> 3;                 // q index within CTA
    const int wl = w & 7;
    const int q0 = blockIdx.x * 2;
    const uint32_t smb = (uint32_t)__cvta_generic_to_shared(smraw);

    // prefetch A chunks 0..2 (3 groups)
    #pragma unroll
    for (int pc = 0; pc < 3; pc++) {
        for (int j = tid; j < CHUNK_BYTES / 16; j += 512)
            cp_async16(smb + OB_A + pc * CHUNK_BYTES + j * 16,
                       g_Ah + (size_t)pc * CHUNK_BYTES + j * 16);
        CP_COMMIT();
    }

    // small weights (BN folded into conv1)
    for (int i = tid; i < 125; i += 512) {
        int cc = i / 25;
        smf[OB_W1F/4 + i] = conv1_w[i] * bn_gamma[cc] * rsqrtf(bn_var[cc] + 1e-5f);
        smf[OB_W2/4 + i]  = conv2_w[i];
    }
    if (tid < 5) {
        float scv = bn_gamma[tid] * rsqrtf(bn_var[tid] + 1e-5f);
        smf[OB_B1F/4 + tid] = (conv1_b[tid] - bn_mean[tid]) * scv + bn_beta[tid];
    }
    if (tid < 25) smf[OB_B2S/4 + tid] = conv2_b[tid];

    // ---- stage + normalize + build B for q0, q1 (staging in GH region) ----
    for (int qi = 0; qi < 2; qi++) {
        const float4* fq4 = (const float4*)(ftest + (size_t)(q0 + qi) * TILE);
        float4* st4 = (float4*)(smraw + OB_GH);
        __syncthreads();
        for (int i = tid; i < 4000; i += 512) st4[i] = fq4[i];
        __syncthreads();
        const float* fqs = (const float*)(smraw + OB_GH);
        for (int s = w; s < SS; s += 16) {
            float acc = 0.f;
            #pragma unroll
            for (int k = 0; k < 20; k++) { float v = fqs[(lane + 32 * k) * SS + s]; acc += v * v; }
            acc = warp_sum(acc);
            if (lane == 0) smf[OB_NINV/4 + qi * 25 + s] = 1.f / fmaxf(sqrtf(acc), 1e-12f);
        }
        __syncthreads();
        // B rows: 25 x 320 half2 (4B stores)
        for (int i = tid; i < 8000; i += 512) {
            int s = i / 320, c2 = i - s * 320;
            float iv = smf[OB_NINV/4 + qi * 25 + s];
            __half2 v = __floats2half2_rn(fqs[(2 * c2) * SS + s] * iv,
                                          fqs[(2 * c2 + 1) * SS + s] * iv);
            *(__half2*)(smraw + OB_B + qi * BQ_B + (s * 648 + 2 * c2) * 2) = v;
        }
    }
    __syncthreads();

    // ---- GEMM: each warp 5 m-tiles x 4 n-tiles for its q ----
    float acc[5][4][4];
    #pragma unroll
    for (int t = 0; t < 5; t++)
        #pragma unroll
        for (int n = 0; n < 4; n++)
            #pragma unroll
            for (int e = 0; e < 4; e++) acc[t][n][e] = 0.f;

    const int nrow = lane >> 2;
    const int kq   = lane & 3;
    const uint32_t bqbase = OB_B + h * BQ_B;

    for (int i = 0; i < NKC; i++) {
        CP_WAIT2();            // chunks newer than i may be in flight; chunk i resident
        __syncthreads();
        if (i + 3 < NKC) {
            int b = (i + 3) % NRING;
            for (int j = tid; j < CHUNK_BYTES / 16; j += 512)
                cp_async16(smb + OB_A + b * CHUNK_BYTES + j * 16,
                           g_Ah + (size_t)(i + 3) * CHUNK_BYTES + j * 16);
        }
        CP_COMMIT();           // commit every iteration (group may be empty)
        const uint32_t abase = smb + OB_A + (i % NRING) * CHUNK_BYTES;

        uint32_t bf[4][2];
        #pragma unroll
        for (int nt = 0; nt < 3; nt++) {
            int n = nt * 8 + nrow;
            uint32_t bidx = bqbase + (uint32_t)(n * 648 + i * 16 + kq * 2) * 2;
            bf[nt][0] = *(const uint32_t*)(smraw + bidx);
            bf[nt][1] = *(const uint32_t*)(smraw + bidx + 16);
        }
        if (nrow == 0) {       // only n=24 valid in last n-tile
            uint32_t bidx = bqbase + (uint32_t)(24 * 648 + i * 16 + kq * 2) * 2;
            bf[3][0] = *(const uint32_t*)(smraw + bidx);
            bf[3][1] = *(const uint32_t*)(smraw + bidx + 16);
        } else {
            bf[3][0] = 0u; bf[3][1] = 0u;
        }

        #pragma unroll
        for (int j = 0; j < 5; j++) {
            int mt = wl + 8 * j;
            int m = mt * 16 + (lane & 15);
            uint32_t addr = abase + m * 32 + ((((lane >> 4) ^ (m >> 2)) & 1) << 4);
            uint32_t a0, a1, a2, a3;
            ldsm_x4(a0, a1, a2, a3, addr);
            #pragma unroll
            for (int nt = 0; nt < 4; nt++)
                mma16816(acc[j][nt][0], acc[j][nt][1], acc[j][nt][2], acc[j][nt][3],
                         a0, a1, a2, a3, bf[nt][0], bf[nt][1]);
        }
    }

    // ---- store G (fp16, per-half buffer) ----
    {
        __half* gh = (__half*)(smraw + OB_GH + h * GH_STRIDE_Q);
        #pragma unroll
        for (int j = 0; j < 5; j++) {
            int mt = wl + 8 * j;
            int r0 = mt * 16 + (lane >> 2);
            int r1 = r0 + 8;
            #pragma unroll
            for (int nt = 0; nt < 4; nt++) {
                int c = nt * 8 + (lane & 3) * 2;
                if (c + 1 < 25) {
                    if (r0 < 625)
                        *(__half2*)(gh + r0 * 26 + c) = __floats2half2_rn(acc[j][nt][0], acc[j][nt][1]);
                    if (r1 < 625)
                        *(__half2*)(gh + r1 * 26 + c) = __floats2half2_rn(acc[j][nt][2], acc[j][nt][3]);
                } else if (c < 25) {
                    if (r0 < 625) gh[r0 * 26 + c] = __float2half_rn(acc[j][nt][0]);
                    if (r1 < 625) gh[r1 * 26 + c] = __float2half_rn(acc[j][nt][2]);
                }
            }
        }
    }
    asm volatile("bar.sync %0, 256;" :: "r"(h + 1) : "memory");

    // ---- per-p epilogue: halves fully parallel ----
    const int q = q0 + h;
    const __half* gh = (const __half*)(smraw + OB_GH + h * GH_STRIDE_Q);
    for (int p = wl; p < PP; p += 8) {
        float* kn = smf + KNI + w * 112;
        if (lane < 25) {
            float a1 = 0.f, a2 = 0.f;
            int rowb = (p * 25 + lane) * 26;
            int colb = p * 25 * 26 + lane;
            #pragma unroll
            for (int j = 0; j < 25; j++) {
                a1 += __half2float(gh[rowb + j]);
                a2 += __half2float(gh[colb + j * 26]);
            }
            kn[lane]      = a1 * (1.f / 25.f);   // g1
            kn[25 + lane] = a2 * (1.f / 25.f);   // g2
        }
        __syncwarp();
        if (lane < 5) {
            float a = smf[OB_B1F/4 + lane];
            #pragma unroll
            for (int j = 0; j < 25; j++) a += kn[j] * smf[OB_W1F/4 + lane * 25 + j];
            kn[50 + lane] = fmaxf(a, 0.f);
        } else if (lane >= 8 && lane < 13) {
            int ii = lane - 8;
            float a = smf[OB_B1F/4 + ii];
            #pragma unroll
            for (int j = 0; j < 25; j++) a += kn[25 + j] * smf[OB_W1F/4 + ii * 25 + j];
            kn[55 + ii] = fmaxf(a, 0.f);
        }
        __syncwarp();
        if (lane < 25) {
            float a1 = smf[OB_B2S/4 + lane], a2 = a1;
            #pragma unroll
            for (int ii = 0; ii < 5; ii++) {
                float wv = smf[OB_W2/4 + lane * 5 + ii];
                a1 += kn[50 + ii] * wv;
                a2 += kn[55 + ii] * wv;
            }
            kn[60 + lane] = fmaxf(a1, 0.f);  // k1
            kn[85 + lane] = fmaxf(a2, 0.f);  // k2
        }
        __syncwarp();
        if (lane < 25) {
            float att1 = 0.f, attt = 0.f;
            int colb = p * 25 * 26 + lane;
            int rowb = (p * 25 + lane) * 26;
            #pragma unroll
            for (int j = 0; j < 25; j++) {
                att1 += kn[60 + j] * __half2float(gh[colb + j * 26]);
                attt += __half2float(gh[rowb + j]) * kn[85 + j];
            }
            g_att1[(size_t)(p * QQ + q) * SS + lane] = att1;
            smf[ATI + h * 625 + p * 25 + lane] = attt;
        }
    }
    asm volatile("bar.sync %0, 256;" :: "r"(h + 1) : "memory");

    // am softmax (warp wl==0) + cls softmax (warp wl==1), per half
    if (wl == 0) {
        float val = 0.f;
        if (lane < 25) {
            #pragma unroll
            for (int j = 0; j < 25; j++) val += smf[ATI + h * 625 + j * 25 + lane];
            val *= (1.f / 25.f);
        }
        float m = (lane < 25) ? val : -1e30f;
        #pragma unroll
        for (int o = 16; o; o >>= 1) m = fmaxf(m, __shfl_xor_sync(0xffffffffu, m, o));
        float e = (lane < 25) ? expf(val - m) : 0.f;
        float ssum = e;
        #pragma unroll
        for (int o = 16; o; o >>= 1) ssum += __shfl_xor_sync(0xffffffffu, ssum, o);
        float a = e / ssum;
        if (lane < 25) {
            out[OFT_AM + q * SS + lane] = a;
            smf[OB_TS/4 + h * 25 + lane] = a + 1.f;
        }
    } else if (wl == 1) {
        float rs = 0.f;
        if (lane < 25) {
            #pragma unroll
            for (int j = 0; j < 25; j++) rs += smf[ATI + h * 625 + lane * 25 + j];
        }
        int g = (lane < 5) ? lane : 4;
        float cg = 0.f;
        #pragma unroll
        for (int i = 0; i < 5; i++) cg += __shfl_sync(0xffffffffu, rs, g * 5 + i);
        cg *= (1.f / 125.f);
        float m = (lane < 5) ? cg : -1e30f;
        #pragma unroll
        for (int o = 4; o; o >>= 1) m = fmaxf(m, __shfl_xor_sync(0xffffffffu, m, o));
        float e = (lane < 5) ? expf(cg - m) : 0.f;
        float ssum = e;
        #pragma unroll
        for (int o = 4; o; o >>= 1) ssum += __shfl_xor_sync(0xffffffffu, ssum, o);
        if (lane < 5) out[OFT_CLS + q * 5 + lane] = e / ssum;
    }
    asm volatile("bar.sync %0, 256;" :: "r"(h + 1) : "memory");

    // ftest_out = raw ftest * (am + 1), each half writes its q
    {
        const int t2 = tid & 255;
        const float4* fq4 = (const float4*)(ftest + (size_t)q * TILE);
        float4* outq = (float4*)(out + OFT_TE + (size_t)q * TILE);
        for (int i = t2; i < 4000; i += 256) {
            float4 b = fq4[i];
            int s = (i * 4) % 25;
            float4 o;
            o.x = b.x * smf[OB_TS/4 + h * 25 + s]; s = (s == 24) ? 0 : s + 1;
            o.y = b.y * smf[OB_TS/4 + h * 25 + s]; s = (s == 24) ? 0 : s + 1;
            o.z = b.z * smf[OB_TS/4 + h * 25 + s]; s = (s == 24) ? 0 : s + 1;
            o.w = b.w * smf[OB_TS/4 + h * 25 + s];
            outq[i] = o;
        }
    }
}

// ---------------- K3a: partial reduce of att1 over q slices ----------------
__global__ void __launch_bounds__(128) cam_final1() {
    __shared__ float bins[128 * 25];
    int p = blockIdx.x >> 3, sl = blockIdx.x & 7;
    int tid = threadIdx.x, lane = tid & 31, w = tid >> 5;
    for (int i = 0; i < 25; i++) bins[tid * 25 + i] = 0.f;
    __syncthreads();
    const float2* a2 = (const float2*)(g_att1 + (size_t)p * QQ * SS + sl * 6250);
    for (int jj = tid; jj < 3125; jj += 128) {
        float2 v = a2[jj];
        int s = (jj * 2) % 25;
        bins[tid * 25 + s] += v.x; s = (s == 24) ? 0 : s + 1;
        bins[tid * 25 + s] += v.y;
    }
    __syncthreads();
    for (int s = w; s < 25; s += 4) {
        float acc = 0.f;
        #pragma unroll
        for (int t = 0; t < 4; t++) acc += bins[(lane + 32 * t) * 25 + s];
        acc = warp_sum(acc);
        if (lane == 0) g_part[blockIdx.x * 25 + s] = acc;
    }
}

// ---------------- K3b: combine, softmax, ftrain_out ----------------
__global__ void __launch_bounds__(256) cam_final2(const float* __restrict__ ftrain,
                                                  float* __restrict__ out) {
    __shared__ float att_s[SS];
    int p = blockIdx.x, tid = threadIdx.x, lane = tid & 31, w = tid >> 5;
    if (w == 0) {
        float val = 0.f;
        if (lane < 25) {
            #pragma unroll
            for (int k = 0; k < 8; k++) val += g_part[(p * 8 + k) * 25 + lane];
            val *= (1.f / (float)QQ);
        }
        float m = (lane < 25) ? val : -1e30f;
        #pragma unroll
        for (int o = 16; o; o >>= 1) m = fmaxf(m, __shfl_xor_sync(0xffffffffu, m, o));
        float e = (lane < 25) ? expf(val - m) : 0.f;
        float ssum = e;
        #pragma unroll
        for (int o = 16; o; o >>= 1) ssum += __shfl_xor_sync(0xffffffffu, ssum, o);
        if (lane < 25) att_s[lane] = e / ssum + 1.f;
    }
    __syncthreads();
    const float4* fp4 = (const float4*)(ftrain + p * TILE);
    float4* outp = (float4*)(out + (size_t)p * TILE);
    for (int i = tid; i < 4000; i += 256) {
        float4 b = fp4[i];
        int s = (i * 4) % 25;
        float4 o;
        o.x = b.x * att_s[s]; s = (s == 24) ? 0 : s + 1;
        o.y = b.y * att_s[s]; s = (s == 24) ? 0 : s + 1;
        o.z = b.z * att_s[s]; s = (s == 24) ? 0 : s + 1;
        o.w = b.w * att_s[s];
        outp[i] = o;
    }
}

// ---------------- launch ----------------
extern "C" void kernel_launch(void* const* d_in, const int* in_sizes, int n_in,
                              void* d_out, int out_size) {
    const float* ftrain  = (const float*)d_in[0];
    const float* ftest   = (const float*)d_in[1];
    const float* conv1_w = (const float*)d_in[6];
    const float* conv1_b = (const float*)d_in[7];
    const float* bn_gamma= (const float*)d_in[8];
    const float* bn_beta = (const float*)d_in[9];
    const float* bn_mean = (const float*)d_in[10];
    const float* bn_var  = (const float*)d_in[11];
    const float* conv2_w = (const float*)d_in[12];
    const float* conv2_b = (const float*)d_in[13];
    float* out = (float*)d_out;

    const int prepA_smem = 64128 + 32000;
    cudaFuncSetAttribute(cam_prep_A, cudaFuncAttributeMaxDynamicSharedMemorySize, prepA_smem);
    cudaFuncSetAttribute(cam_main,   cudaFuncAttributeMaxDynamicSharedMemorySize, SMEM_BYTES);

    cam_prep_A<<<PP, 256, prepA_smem>>>(ftrain);
    cam_main<<<QQ / 2, 512, SMEM_BYTES>>>(ftest, conv1_w, conv1_b, bn_gamma, bn_beta,
                                          bn_mean, bn_var, conv2_w, conv2_b, out);
    cam_final1<<<200, 128>>>();
    cam_final2<<<PP, 256>>>(ftrain, out);
}

// round 8
// speedup vs baseline: 1.4023x; 1.1156x over previous
#include <cuda_runtime.h>
#include <cuda_fp16.h>
#include <math.h>
#include <stdint.h>

// ---------------- problem constants ----------------
#define PP   25
#define QQ   2000
#define CC   640
#define SS   25
#define TILE 16000          // CC*SS floats

#define MPAD 640            // Gram rows padded (625 valid)
#define NKC  40             // K chunks of 16
#define CHUNK_BYTES (MPAD * 32)   // 20480 B
#define NRING 4
#define BQ_B  32400         // 25 rows x 648 halves x 2B
#define AT1S  632           // g_att1 floats per q (625 + pad to 16B)

// output layout: [ftrain_out 400000][ftest_out 32000000][am 50000][cls 10000]
#define OFT_TE  400000
#define OFT_AM  32400000
#define OFT_CLS 32450000

// ---------------- device scratch ----------------
__device__ __align__(16) unsigned char g_Ah[NKC * CHUNK_BYTES]; // swizzled fp16 A image
__device__ __align__(16) float g_att1[QQ * AT1S];               // att1[q][p*25+s]
__device__ float g_part[200 * SS];                              // partials for final

// ---------------- smem byte offsets (cam_main) ----------------
#define OB_A     0        // 81920: A ring 4x20480; then G fp16 2x32512; then fq1/out1
#define OB_B     81920    // 64800: B0,B1; then fq0/out0 (64000)
#define OB_AT1   146720   // 2 x 632 x 4 = 5056
#define OB_ATT   151776   // 2 x 625 x 4 = 5000
#define OB_KN    156776   // 16 x 112 x 4 = 7168
#define OB_W1F   163944   // 125 f
#define OB_W2    164444   // 125 f
#define OB_B1F   164944   // 5 f
#define OB_B2S   164964   // 25 f
#define OB_NINV  165064   // 2 x 25 f
#define OB_TS    165264   // 2 x 25 f
#define OB_MBAR  165472   // 8 mbarriers x 8B
#define SMEM_BYTES 165536

#define GH_STRIDE 32512

#define AT1I (OB_AT1/4)
#define ATI  (OB_ATT/4)
#define KNI  (OB_KN/4)

__device__ __forceinline__ float warp_sum(float v) {
    #pragma unroll
    for (int o = 16; o; o >>= 1) v += __shfl_xor_sync(0xffffffffu, v, o);
    return v;
}
__device__ __forceinline__ void mbar_init(uint32_t mbar, uint32_t cnt) {
    asm volatile("mbarrier.init.shared.b64 [%0], %1;" :: "r"(mbar), "r"(cnt) : "memory");
}
__device__ __forceinline__ void mbar_expect_tx(uint32_t mbar, uint32_t bytes) {
    asm volatile("mbarrier.arrive.expect_tx.shared.b64 _, [%0], %1;"
                 :: "r"(mbar), "r"(bytes) : "memory");
}
__device__ __forceinline__ void mbar_wait(uint32_t mbar, uint32_t parity) {
    asm volatile(
        "{\n\t.reg .pred P;\n\t"
        "W_%=:\n\t"
        "mbarrier.try_wait.parity.acquire.cta.shared::cta.b64 P, [%0], %1, 0x989680;\n\t"
        "@P bra D_%=;\n\t"
        "bra.uni W_%=;\n\t"
        "D_%=:\n\t}"
        :: "r"(mbar), "r"(parity) : "memory");
}
__device__ __forceinline__ void bulk_ld(uint32_t dst, const void* src, uint32_t bytes,
                                        uint32_t mbar) {
    asm volatile("cp.async.bulk.shared::cluster.global.mbarrier::complete_tx::bytes "
                 "[%0], [%1], %2, [%3];"
                 :: "r"(dst), "l"(src), "r"(bytes), "r"(mbar) : "memory");
}
__device__ __forceinline__ void bulk_st(void* gdst, uint32_t ssrc, uint32_t bytes) {
    asm volatile("cp.async.bulk.global.shared::cta.bulk_group [%0], [%1], %2;"
                 :: "l"(gdst), "r"(ssrc), "r"(bytes) : "memory");
}
#define BULK_COMMIT() asm volatile("cp.async.bulk.commit_group;" ::: "memory")
#define BULK_WAIT0()  asm volatile("cp.async.bulk.wait_group 0;" ::: "memory")
#define FENCE_ASYNC() asm volatile("fence.proxy.async.shared::cta;" ::: "memory")

__device__ __forceinline__ void ldsm_x4(uint32_t& r0, uint32_t& r1, uint32_t& r2, uint32_t& r3,
                                        uint32_t addr) {
    asm volatile("ldmatrix.sync.aligned.m8n8.x4.shared.b16 {%0,%1,%2,%3}, [%4];"
                 : "=r"(r0), "=r"(r1), "=r"(r2), "=r"(r3) : "r"(addr));
}
__device__ __forceinline__ void mma16816(float& d0, float& d1, float& d2, float& d3,
                                         uint32_t a0, uint32_t a1, uint32_t a2, uint32_t a3,
                                         uint32_t b0, uint32_t b1) {
    asm volatile("mma.sync.aligned.m16n8k16.row.col.f32.f16.f16.f32 "
                 "{%0,%1,%2,%3}, {%4,%5,%6,%7}, {%8,%9}, {%0,%1,%2,%3};"
                 : "+f"(d0), "+f"(d1), "+f"(d2), "+f"(d3)
                 : "r"(a0), "r"(a1), "r"(a2), "r"(a3), "r"(b0), "r"(b1));
}

// ---------------- K1: build swizzled fp16 A image ----------------
__global__ void __launch_bounds__(256) cam_prep_A(const float* __restrict__ ftrain) {
    extern __shared__ float sm[];
    float* xs    = sm;                       // 16000 f
    float* inv_s = sm + 16000;               // 25 f
    unsigned char* buf = (unsigned char*)sm + 64128;  // 32000 B
    int p = blockIdx.x, tid = threadIdx.x, lane = tid & 31, w = tid >> 5;
    const float4* fp4 = (const float4*)(ftrain + p * TILE);
    float4* xs4 = (float4*)xs;
    for (int i = tid; i < 4000; i += 256) xs4[i] = fp4[i];
    __syncthreads();
    for (int s = w; s < SS; s += 8) {
        float acc = 0.f;
        #pragma unroll
        for (int k = 0; k < 20; k++) { float v = xs[(lane + 32 * k) * SS + s]; acc += v * v; }
        acc = warp_sum(acc);
        if (lane == 0) inv_s[s] = 1.f / fmaxf(sqrtf(acc), 1e-12f);
    }
    __syncthreads();
    for (int idx = tid; idx < TILE; idx += 256) {
        int c = idx / SS, s = idx - c * SS;
        __half v = __float2half_rn(xs[idx] * inv_s[s]);
        int m = p * SS + s;
        int kc = c >> 4, k = c & 15;
        uint32_t off = (uint32_t)((((k >> 3) ^ ((m >> 2) & 1)) << 4) + ((k & 7) << 1));
        *(__half*)(buf + kc * 800 + s * 32 + off) = v;
    }
    __syncthreads();
    for (int i = tid; i < 2000; i += 256) {
        int kc = i / 50, j = i - kc * 50;
        *(float4*)(g_Ah + (size_t)(kc * MPAD + p * SS) * 32 + j * 16) =
            *(const float4*)(buf + kc * 800 + j * 16);
    }
}

// ---------------- K2: main kernel, 2 q per CTA, bulk-async data movement ----------------
__global__ void __launch_bounds__(512, 1) cam_main(
    const float* __restrict__ ftest,
    const float* __restrict__ conv1_w, const float* __restrict__ conv1_b,
    const float* __restrict__ bn_gamma, const float* __restrict__ bn_beta,
    const float* __restrict__ bn_mean, const float* __restrict__ bn_var,
    const float* __restrict__ conv2_w, const float* __restrict__ conv2_b,
    float* __restrict__ out)
{
    extern __shared__ char smraw[];
    float* smf = (float*)smraw;
    const int tid = threadIdx.x, lane = tid & 31, w = tid >> 5;
    const int h = w >> 3;                 // q index within CTA (0/1)
    const int wl = w & 7;                 // warp within half
    const int q0 = blockIdx.x * 2;
    const int q = q0 + h;
    const uint32_t smb = (uint32_t)__cvta_generic_to_shared(smraw);
    const uint32_t MB = smb + OB_MBAR;

    if (tid == 0) {
        #pragma unroll
        for (int b = 0; b < 8; b++) mbar_init(MB + b * 8, 1);
    }
    // small weights (BN folded into conv1)
    for (int i = tid; i < 125; i += 512) {
        int cc = i / 25;
        smf[OB_W1F/4 + i] = conv1_w[i] * bn_gamma[cc] * rsqrtf(bn_var[cc] + 1e-5f);
        smf[OB_W2/4 + i]  = conv2_w[i];
    }
    if (tid < 5) {
        float scv = bn_gamma[tid] * rsqrtf(bn_var[tid] + 1e-5f);
        smf[OB_B1F/4 + tid] = (conv1_b[tid] - bn_mean[tid]) * scv + bn_beta[tid];
    }
    if (tid < 25) smf[OB_B2S/4 + tid] = conv2_b[tid];
    __syncthreads();   // mbarrier init visible before any use

    // ---- setup: stage fq (bulk), norms, build B (per q, sequential) ----
    for (int qi = 0; qi < 2; qi++) {
        if (tid == 0) {
            mbar_expect_tx(MB + (4 + qi) * 8, TILE * 4);
            bulk_ld(smb + OB_A, ftest + (size_t)(q0 + qi) * TILE, TILE * 4, MB + (4 + qi) * 8);
        }
        mbar_wait(MB + (4 + qi) * 8, 0);
        const float* fqs = (const float*)(smraw + OB_A);
        for (int s = w; s < SS; s += 16) {
            float acc = 0.f;
            #pragma unroll
            for (int k = 0; k < 20; k++) { float v = fqs[(lane + 32 * k) * SS + s]; acc += v * v; }
            acc = warp_sum(acc);
            if (lane == 0) smf[OB_NINV/4 + qi * 25 + s] = 1.f / fmaxf(sqrtf(acc), 1e-12f);
        }
        __syncthreads();
        for (int i = tid; i < 8000; i += 512) {
            int s = i / 320, c2 = i - s * 320;
            float iv = smf[OB_NINV/4 + qi * 25 + s];
            __half2 v = __floats2half2_rn(fqs[(2 * c2) * SS + s] * iv,
                                          fqs[(2 * c2 + 1) * SS + s] * iv);
            *(__half2*)(smraw + OB_B + qi * BQ_B + (s * 648 + 2 * c2) * 2) = v;
        }
        __syncthreads();   // staging region free for next phase
    }

    // ---- start A stream (bulk ring, prefetch 3) ----
    if (tid == 0) {
        #pragma unroll
        for (int pc = 0; pc < 3; pc++) {
            mbar_expect_tx(MB + pc * 8, CHUNK_BYTES);
            bulk_ld(smb + OB_A + pc * CHUNK_BYTES, g_Ah + (size_t)pc * CHUNK_BYTES,
                    CHUNK_BYTES, MB + pc * 8);
        }
    }

    // ---- GEMM: each warp 5 m-tiles x 4 n-tiles for its q ----
    float acc[5][4][4];
    #pragma unroll
    for (int t = 0; t < 5; t++)
        #pragma unroll
        for (int n = 0; n < 4; n++)
            #pragma unroll
            for (int e = 0; e < 4; e++) acc[t][n][e] = 0.f;

    const int nrow = lane >> 2;
    const int kq   = lane & 3;
    const uint32_t bqbase = OB_B + h * BQ_B;

    for (int i = 0; i < NKC; i++) {
        __syncthreads();                          // prior reads of slot (i+3)&3 done
        if (tid == 0 && i + 3 < NKC) {
            int b = (i + 3) & 3;
            mbar_expect_tx(MB + b * 8, CHUNK_BYTES);
            bulk_ld(smb + OB_A + b * CHUNK_BYTES, g_Ah + (size_t)(i + 3) * CHUNK_BYTES,
                    CHUNK_BYTES, MB + b * 8);
        }
        mbar_wait(MB + (i & 3) * 8, (i >> 2) & 1);
        const uint32_t abase = smb + OB_A + (i & 3) * CHUNK_BYTES;

        uint32_t bf[4][2];
        #pragma unroll
        for (int nt = 0; nt < 3; nt++) {
            int n = nt * 8 + nrow;
            uint32_t bidx = bqbase + (uint32_t)(n * 648 + i * 16 + kq * 2) * 2;
            bf[nt][0] = *(const uint32_t*)(smraw + bidx);
            bf[nt][1] = *(const uint32_t*)(smraw + bidx + 16);
        }
        if (nrow == 0) {   // only n=24 valid in last n-tile
            uint32_t bidx = bqbase + (uint32_t)(24 * 648 + i * 16 + kq * 2) * 2;
            bf[3][0] = *(const uint32_t*)(smraw + bidx);
            bf[3][1] = *(const uint32_t*)(smraw + bidx + 16);
        } else {
            bf[3][0] = 0u; bf[3][1] = 0u;
        }

        #pragma unroll
        for (int j = 0; j < 5; j++) {
            int mt = wl + 8 * j;
            int m = mt * 16 + (lane & 15);
            uint32_t addr = abase + m * 32 + ((((lane >> 4) ^ (m >> 2)) & 1) << 4);
            uint32_t a0, a1, a2, a3;
            ldsm_x4(a0, a1, a2, a3, addr);
            #pragma unroll
            for (int nt = 0; nt < 4; nt++)
                mma16816(acc[j][nt][0], acc[j][nt][1], acc[j][nt][2], acc[j][nt][3],
                         a0, a1, a2, a3, bf[nt][0], bf[nt][1]);
        }
    }
    __syncthreads();   // ring + B operands dead

    // prefetch raw fq0 for output into B region (overlaps epilogue)
    if (tid == 0) {
        mbar_expect_tx(MB + 6 * 8, TILE * 4);
        bulk_ld(smb + OB_B, ftest + (size_t)q0 * TILE, TILE * 4, MB + 6 * 8);
    }

    // ---- store G (fp16, per-half buffer in dead A region) ----
    {
        __half* gh = (__half*)(smraw + OB_A + h * GH_STRIDE);
        #pragma unroll
        for (int j = 0; j < 5; j++) {
            int mt = wl + 8 * j;
            int r0 = mt * 16 + (lane >> 2);
            int r1 = r0 + 8;
            #pragma unroll
            for (int nt = 0; nt < 4; nt++) {
                int c = nt * 8 + (lane & 3) * 2;
                if (c + 1 < 25) {
                    if (r0 < 625)
                        *(__half2*)(gh + r0 * 26 + c) = __floats2half2_rn(acc[j][nt][0], acc[j][nt][1]);
                    if (r1 < 625)
                        *(__half2*)(gh + r1 * 26 + c) = __floats2half2_rn(acc[j][nt][2], acc[j][nt][3]);
                } else if (c < 25) {
                    if (r0 < 625) gh[r0 * 26 + c] = __float2half_rn(acc[j][nt][0]);
                    if (r1 < 625) gh[r1 * 26 + c] = __float2half_rn(acc[j][nt][2]);
                }
            }
        }
    }
    asm volatile("bar.sync %0, 256;" :: "r"(h + 1) : "memory");

    // ---- per-p epilogue (halves parallel) ----
    {
        const __half* gh = (const __half*)(smraw + OB_A + h * GH_STRIDE);
        for (int p = wl; p < PP; p += 8) {
            float* kn = smf + KNI + w * 112;
            if (lane < 25) {
                float a1 = 0.f, a2 = 0.f;
                int rowb = (p * 25 + lane) * 26;
                int colb = p * 25 * 26 + lane;
                #pragma unroll
                for (int j = 0; j < 25; j++) {
                    a1 += __half2float(gh[rowb + j]);
                    a2 += __half2float(gh[colb + j * 26]);
                }
                kn[lane]      = a1 * (1.f / 25.f);   // g1
                kn[25 + lane] = a2 * (1.f / 25.f);   // g2
            }
            __syncwarp();
            if (lane < 5) {
                float a = smf[OB_B1F/4 + lane];
                #pragma unroll
                for (int j = 0; j < 25; j++) a += kn[j] * smf[OB_W1F/4 + lane * 25 + j];
                kn[50 + lane] = fmaxf(a, 0.f);
            } else if (lane >= 8 && lane < 13) {
                int ii = lane - 8;
                float a = smf[OB_B1F/4 + ii];
                #pragma unroll
                for (int j = 0; j < 25; j++) a += kn[25 + j] * smf[OB_W1F/4 + ii * 25 + j];
                kn[55 + ii] = fmaxf(a, 0.f);
            }
            __syncwarp();
            if (lane < 25) {
                float a1 = smf[OB_B2S/4 + lane], a2 = a1;
                #pragma unroll
                for (int ii = 0; ii < 5; ii++) {
                    float wv = smf[OB_W2/4 + lane * 5 + ii];
                    a1 += kn[50 + ii] * wv;
                    a2 += kn[55 + ii] * wv;
                }
                kn[60 + lane] = fmaxf(a1, 0.f);  // k1
                kn[85 + lane] = fmaxf(a2, 0.f);  // k2
            }
            __syncwarp();
            if (lane < 25) {
                float att1 = 0.f, attt = 0.f;
                int colb = p * 25 * 26 + lane;
                int rowb = (p * 25 + lane) * 26;
                #pragma unroll
                for (int j = 0; j < 25; j++) {
                    att1 += kn[60 + j] * __half2float(gh[colb + j * 26]);
                    attt += __half2float(gh[rowb + j]) * kn[85 + j];
                }
                smf[AT1I + h * AT1S + p * 25 + lane] = att1;
                smf[ATI + h * 625 + p * 25 + lane]   = attt;
            }
        }
    }
    __syncthreads();   // both halves done with G (whole A region dead)

    // prefetch raw fq1 for output into A region
    if (tid == 0) {
        mbar_expect_tx(MB + 7 * 8, TILE * 4);
        bulk_ld(smb + OB_A, ftest + (size_t)(q0 + 1) * TILE, TILE * 4, MB + 7 * 8);
    }

    // ---- softmaxes (per half: warp wl==0 am, wl==1 cls) ----
    if (wl == 0) {
        float val = 0.f;
        if (lane < 25) {
            #pragma unroll
            for (int j = 0; j < 25; j++) val += smf[ATI + h * 625 + j * 25 + lane];
            val *= (1.f / 25.f);
        }
        float m = (lane < 25) ? val : -1e30f;
        #pragma unroll
        for (int o = 16; o; o >>= 1) m = fmaxf(m, __shfl_xor_sync(0xffffffffu, m, o));
        float e = (lane < 25) ? expf(val - m) : 0.f;
        float ssum = e;
        #pragma unroll
        for (int o = 16; o; o >>= 1) ssum += __shfl_xor_sync(0xffffffffu, ssum, o);
        float a = e / ssum;
        if (lane < 25) {
            out[OFT_AM + q * SS + lane] = a;
            smf[OB_TS/4 + h * 25 + lane] = a + 1.f;
        }
    } else if (wl == 1) {
        float rs = 0.f;
        if (lane < 25) {
            #pragma unroll
            for (int j = 0; j < 25; j++) rs += smf[ATI + h * 625 + lane * 25 + j];
        }
        int g = (lane < 5) ? lane : 4;
        float cg = 0.f;
        #pragma unroll
        for (int i = 0; i < 5; i++) cg += __shfl_sync(0xffffffffu, rs, g * 5 + i);
        cg *= (1.f / 125.f);
        float m = (lane < 5) ? cg : -1e30f;
        #pragma unroll
        for (int o = 4; o; o >>= 1) m = fmaxf(m, __shfl_xor_sync(0xffffffffu, m, o));
        float e = (lane < 5) ? expf(cg - m) : 0.f;
        float ssum = e;
        #pragma unroll
        for (int o = 4; o; o >>= 1) ssum += __shfl_xor_sync(0xffffffffu, ssum, o);
        if (lane < 5) out[OFT_CLS + q * 5 + lane] = e / ssum;
    }
    asm volatile("bar.sync %0, 256;" :: "r"(h + 1) : "memory");  // TS[h] ready

    // ---- output: half h scales its fq in smem, bulk-stores out + att1 ----
    {
        const uint32_t stage_off = (h == 0) ? OB_B : OB_A;
        mbar_wait(MB + (6 + h) * 8, 0);
        float4* st4 = (float4*)(smraw + stage_off);
        const int t2 = tid & 255;
        for (int i = t2; i < 4000; i += 256) {
            float4 b = st4[i];
            int s = (i * 4) % 25;
            b.x *= smf[OB_TS/4 + h * 25 + s]; s = (s == 24) ? 0 : s + 1;
            b.y *= smf[OB_TS/4 + h * 25 + s]; s = (s == 24) ? 0 : s + 1;
            b.z *= smf[OB_TS/4 + h * 25 + s]; s = (s == 24) ? 0 : s + 1;
            b.w *= smf[OB_TS/4 + h * 25 + s];
            st4[i] = b;
        }
        asm volatile("bar.sync %0, 256;" :: "r"(h + 1) : "memory");
        if (t2 == 0) {
            FENCE_ASYNC();
            bulk_st(out + OFT_TE + (size_t)q * TILE, smb + stage_off, TILE * 4);
            bulk_st(g_att1 + (size_t)q * AT1S, smb + OB_AT1 + h * (AT1S * 4), AT1S * 4);
            BULK_COMMIT();
            BULK_WAIT0();
        }
    }
    __syncthreads();   // keep smem alive until bulk stores complete
}

// ---------------- K3a: partial reduce of att1 over q slices ----------------
__global__ void __launch_bounds__(128) cam_final1() {
    __shared__ float red[125];
    int p = blockIdx.x >> 3, sl = blockIdx.x & 7;
    int tid = threadIdx.x;
    if (tid < 125) {
        int s = tid % 25, grp = tid / 25;
        const float* base = g_att1 + p * 25 + s;
        float acc = 0.f;
        for (int qq = sl * 250 + grp; qq < (sl + 1) * 250; qq += 5)
            acc += base[(size_t)qq * AT1S];
        red[tid] = acc;
    }
    __syncthreads();
    if (tid < 25) {
        float v = red[tid] + red[25 + tid] + red[50 + tid] + red[75 + tid] + red[100 + tid];
        g_part[blockIdx.x * 25 + tid] = v;
    }
}

// ---------------- K3b: combine, softmax, ftrain_out ----------------
__global__ void __launch_bounds__(256) cam_final2(const float* __restrict__ ftrain,
                                                  float* __restrict__ out) {
    __shared__ float att_s[SS];
    int p = blockIdx.x, tid = threadIdx.x, lane = tid & 31, w = tid >> 5;
    if (w == 0) {
        float val = 0.f;
        if (lane < 25) {
            #pragma unroll
            for (int k = 0; k < 8; k++) val += g_part[(p * 8 + k) * 25 + lane];
            val *= (1.f / (float)QQ);
        }
        float m = (lane < 25) ? val : -1e30f;
        #pragma unroll
        for (int o = 16; o; o >>= 1) m = fmaxf(m, __shfl_xor_sync(0xffffffffu, m, o));
        float e = (lane < 25) ? expf(val - m) : 0.f;
        float ssum = e;
        #pragma unroll
        for (int o = 16; o; o >>= 1) ssum += __shfl_xor_sync(0xffffffffu, ssum, o);
        if (lane < 25) att_s[lane] = e / ssum + 1.f;
    }
    __syncthreads();
    const float4* fp4 = (const float4*)(ftrain + p * TILE);
    float4* outp = (float4*)(out + (size_t)p * TILE);
    for (int i = tid; i < 4000; i += 256) {
        float4 b = fp4[i];
        int s = (i * 4) % 25;
        float4 o;
        o.x = b.x * att_s[s]; s = (s == 24) ? 0 : s + 1;
        o.y = b.y * att_s[s]; s = (s == 24) ? 0 : s + 1;
        o.z = b.z * att_s[s]; s = (s == 24) ? 0 : s + 1;
        o.w = b.w * att_s[s];
        outp[i] = o;
    }
}

// ---------------- launch ----------------
extern "C" void kernel_launch(void* const* d_in, const int* in_sizes, int n_in,
                              void* d_out, int out_size) {
    const float* ftrain  = (const float*)d_in[0];
    const float* ftest   = (const float*)d_in[1];
    const float* conv1_w = (const float*)d_in[6];
    const float* conv1_b = (const float*)d_in[7];
    const float* bn_gamma= (const float*)d_in[8];
    const float* bn_beta = (const float*)d_in[9];
    const float* bn_mean = (const float*)d_in[10];
    const float* bn_var  = (const float*)d_in[11];
    const float* conv2_w = (const float*)d_in[12];
    const float* conv2_b = (const float*)d_in[13];
    float* out = (float*)d_out;

    const int prepA_smem = 64128 + 32000;
    cudaFuncSetAttribute(cam_prep_A, cudaFuncAttributeMaxDynamicSharedMemorySize, prepA_smem);
    cudaFuncSetAttribute(cam_main,   cudaFuncAttributeMaxDynamicSharedMemorySize, SMEM_BYTES);

    cam_prep_A<<<PP, 256, prepA_smem>>>(ftrain);
    cam_main<<<QQ / 2, 512, SMEM_BYTES>>>(ftest, conv1_w, conv1_b, bn_gamma, bn_beta,
                                          bn_mean, bn_var, conv2_w, conv2_b, out);
    cam_final1<<<200, 128>>>();
    cam_final2<<<PP, 256>>>(ftrain, out);
}

// round 9
// speedup vs baseline: 1.4102x; 1.0056x over previous
#include <cuda_runtime.h>
#include <cuda_fp16.h>
#include <math.h>
#include <stdint.h>

// ---------------- problem constants ----------------
#define PP   25
#define QQ   2000
#define CC   640
#define SS   25
#define TILE 16000          // CC*SS floats

#define MPAD 640            // Gram rows padded (625 valid)
#define NKC  40             // K chunks of 16
#define CHUNK_BYTES (MPAD * 32)   // 20480 B
#define BQ_B  32400         // 25 rows x 648 halves x 2B
#define AT1S  632           // g_att1 floats per q (625 + pad to 16B)

// output layout: [ftrain_out 400000][ftest_out 32000000][am 50000][cls 10000]
#define OFT_TE  400000
#define OFT_AM  32400000
#define OFT_CLS 32450000

// ---------------- device scratch ----------------
__device__ __align__(16) unsigned char g_Ah[NKC * CHUNK_BYTES]; // swizzled fp16 A image
__device__ __align__(16) float g_att1[QQ * AT1S];               // att1[q][p*25+s]
__device__ float g_part[200 * SS];                              // partials for final

// ---------------- smem byte offsets (cam_main) ----------------
#define OB_A     0        // 81920: A ring 4x20480; then G fp16 2x32512; then fq1/out1
#define OB_B     81920    // 64800: B0,B1; then fq0/out0 (64000)
#define OB_AT1   146720   // 2 x 632 x 4 = 5056
#define OB_ATT   151776   // 2 x 625 x 4 = 5000
#define OB_KN    156776   // 16 x 112 x 4 = 7168
#define OB_W1F   163944   // 125 f
#define OB_W2    164444   // 125 f
#define OB_B1F   164944   // 5 f
#define OB_B2S   164964   // 25 f
#define OB_NINV  165064   // 2 x 25 f
#define OB_TS    165264   // 2 x 25 f
#define OB_MBAR  165472   // 8 mbarriers x 8B
#define SMEM_BYTES 165536

#define GH_STRIDE 32512

#define AT1I (OB_AT1/4)
#define ATI  (OB_ATT/4)
#define KNI  (OB_KN/4)

__device__ __forceinline__ float warp_sum(float v) {
    #pragma unroll
    for (int o = 16; o; o >>= 1) v += __shfl_xor_sync(0xffffffffu, v, o);
    return v;
}
__device__ __forceinline__ void mbar_init(uint32_t mbar, uint32_t cnt) {
    asm volatile("mbarrier.init.shared.b64 [%0], %1;" :: "r"(mbar), "r"(cnt) : "memory");
}
__device__ __forceinline__ void mbar_expect_tx(uint32_t mbar, uint32_t bytes) {
    asm volatile("mbarrier.arrive.expect_tx.shared.b64 _, [%0], %1;"
                 :: "r"(mbar), "r"(bytes) : "memory");
}
__device__ __forceinline__ void mbar_wait(uint32_t mbar, uint32_t parity) {
    asm volatile(
        "{\n\t.reg .pred P;\n\t"
        "W_%=:\n\t"
        "mbarrier.try_wait.parity.acquire.cta.shared::cta.b64 P, [%0], %1, 0x989680;\n\t"
        "@P bra D_%=;\n\t"
        "bra.uni W_%=;\n\t"
        "D_%=:\n\t}"
        :: "r"(mbar), "r"(parity) : "memory");
}
__device__ __forceinline__ void bulk_ld(uint32_t dst, const void* src, uint32_t bytes,
                                        uint32_t mbar) {
    asm volatile("cp.async.bulk.shared::cluster.global.mbarrier::complete_tx::bytes "
                 "[%0], [%1], %2, [%3];"
                 :: "r"(dst), "l"(src), "r"(bytes), "r"(mbar) : "memory");
}
__device__ __forceinline__ void bulk_st(void* gdst, uint32_t ssrc, uint32_t bytes) {
    asm volatile("cp.async.bulk.global.shared::cta.bulk_group [%0], [%1], %2;"
                 :: "l"(gdst), "r"(ssrc), "r"(bytes) : "memory");
}
#define BULK_COMMIT() asm volatile("cp.async.bulk.commit_group;" ::: "memory")
#define BULK_WAIT0()  asm volatile("cp.async.bulk.wait_group 0;" ::: "memory")
#define FENCE_ASYNC() asm volatile("fence.proxy.async.shared::cta;" ::: "memory")

__device__ __forceinline__ void ldsm_x4(uint32_t& r0, uint32_t& r1, uint32_t& r2, uint32_t& r3,
                                        uint32_t addr) {
    asm volatile("ldmatrix.sync.aligned.m8n8.x4.shared.b16 {%0,%1,%2,%3}, [%4];"
                 : "=r"(r0), "=r"(r1), "=r"(r2), "=r"(r3) : "r"(addr));
}
// f16 accumulators: D,C packed half2 x2
__device__ __forceinline__ void mma16816h(uint32_t& d0, uint32_t& d1,
                                          uint32_t a0, uint32_t a1, uint32_t a2, uint32_t a3,
                                          uint32_t b0, uint32_t b1) {
    asm volatile("mma.sync.aligned.m16n8k16.row.col.f16.f16.f16.f16 "
                 "{%0,%1}, {%2,%3,%4,%5}, {%6,%7}, {%0,%1};"
                 : "+r"(d0), "+r"(d1)
                 : "r"(a0), "r"(a1), "r"(a2), "r"(a3), "r"(b0), "r"(b1));
}

// ---------------- K1: build swizzled fp16 A image ----------------
__global__ void __launch_bounds__(256) cam_prep_A(const float* __restrict__ ftrain) {
    extern __shared__ float sm[];
    float* xs    = sm;                       // 16000 f
    float* inv_s = sm + 16000;               // 25 f
    unsigned char* buf = (unsigned char*)sm + 64128;  // 32000 B
    int p = blockIdx.x, tid = threadIdx.x, lane = tid & 31, w = tid >> 5;
    const float4* fp4 = (const float4*)(ftrain + p * TILE);
    float4* xs4 = (float4*)xs;
    for (int i = tid; i < 4000; i += 256) xs4[i] = fp4[i];
    __syncthreads();
    for (int s = w; s < SS; s += 8) {
        float acc = 0.f;
        #pragma unroll
        for (int k = 0; k < 20; k++) { float v = xs[(lane + 32 * k) * SS + s]; acc += v * v; }
        acc = warp_sum(acc);
        if (lane == 0) inv_s[s] = 1.f / fmaxf(sqrtf(acc), 1e-12f);
    }
    __syncthreads();
    for (int idx = tid; idx < TILE; idx += 256) {
        int c = idx / SS, s = idx - c * SS;
        __half v = __float2half_rn(xs[idx] * inv_s[s]);
        int m = p * SS + s;
        int kc = c >> 4, k = c & 15;
        uint32_t off = (uint32_t)((((k >> 3) ^ ((m >> 2) & 1)) << 4) + ((k & 7) << 1));
        *(__half*)(buf + kc * 800 + s * 32 + off) = v;
    }
    __syncthreads();
    for (int i = tid; i < 2000; i += 256) {
        int kc = i / 50, j = i - kc * 50;
        *(float4*)(g_Ah + (size_t)(kc * MPAD + p * SS) * 32 + j * 16) =
            *(const float4*)(buf + kc * 800 + j * 16);
    }
}

// ---------------- K2: main kernel, 2 q per CTA, bulk-async, f16 accum ----------------
__global__ void __launch_bounds__(512, 1) cam_main(
    const float* __restrict__ ftest,
    const float* __restrict__ conv1_w, const float* __restrict__ conv1_b,
    const float* __restrict__ bn_gamma, const float* __restrict__ bn_beta,
    const float* __restrict__ bn_mean, const float* __restrict__ bn_var,
    const float* __restrict__ conv2_w, const float* __restrict__ conv2_b,
    float* __restrict__ out)
{
    extern __shared__ char smraw[];
    float* smf = (float*)smraw;
    const int tid = threadIdx.x, lane = tid & 31, w = tid >> 5;
    const int h = w >> 3;                 // q index within CTA (0/1)
    const int wl = w & 7;                 // warp within half
    const int q0 = blockIdx.x * 2;
    const int q = q0 + h;
    const uint32_t smb = (uint32_t)__cvta_generic_to_shared(smraw);
    const uint32_t MB = smb + OB_MBAR;

    if (tid == 0) {
        #pragma unroll
        for (int b = 0; b < 8; b++) mbar_init(MB + b * 8, 1);
    }
    for (int i = tid; i < 125; i += 512) {
        int cc = i / 25;
        smf[OB_W1F/4 + i] = conv1_w[i] * bn_gamma[cc] * rsqrtf(bn_var[cc] + 1e-5f);
        smf[OB_W2/4 + i]  = conv2_w[i];
    }
    if (tid < 5) {
        float scv = bn_gamma[tid] * rsqrtf(bn_var[tid] + 1e-5f);
        smf[OB_B1F/4 + tid] = (conv1_b[tid] - bn_mean[tid]) * scv + bn_beta[tid];
    }
    if (tid < 25) smf[OB_B2S/4 + tid] = conv2_b[tid];
    __syncthreads();   // mbarrier init visible

    // ---- setup: stage fq (bulk), norms, build B ----
    for (int qi = 0; qi < 2; qi++) {
        if (tid == 0) {
            mbar_expect_tx(MB + (4 + qi) * 8, TILE * 4);
            bulk_ld(smb + OB_A, ftest + (size_t)(q0 + qi) * TILE, TILE * 4, MB + (4 + qi) * 8);
        }
        mbar_wait(MB + (4 + qi) * 8, 0);
        const float* fqs = (const float*)(smraw + OB_A);
        for (int s = w; s < SS; s += 16) {
            float acc = 0.f;
            #pragma unroll
            for (int k = 0; k < 20; k++) { float v = fqs[(lane + 32 * k) * SS + s]; acc += v * v; }
            acc = warp_sum(acc);
            if (lane == 0) smf[OB_NINV/4 + qi * 25 + s] = 1.f / fmaxf(sqrtf(acc), 1e-12f);
        }
        __syncthreads();
        for (int i = tid; i < 8000; i += 512) {
            int s = i / 320, c2 = i - s * 320;
            float iv = smf[OB_NINV/4 + qi * 25 + s];
            __half2 v = __floats2half2_rn(fqs[(2 * c2) * SS + s] * iv,
                                          fqs[(2 * c2 + 1) * SS + s] * iv);
            *(__half2*)(smraw + OB_B + qi * BQ_B + (s * 648 + 2 * c2) * 2) = v;
        }
        __syncthreads();
    }

    // ---- start A stream (bulk ring, prefetch 3) ----
    if (tid == 0) {
        #pragma unroll
        for (int pc = 0; pc < 3; pc++) {
            mbar_expect_tx(MB + pc * 8, CHUNK_BYTES);
            bulk_ld(smb + OB_A + pc * CHUNK_BYTES, g_Ah + (size_t)pc * CHUNK_BYTES,
                    CHUNK_BYTES, MB + pc * 8);
        }
    }

    // ---- GEMM: each warp 5 m-tiles x 4 n-tiles, fp16 accumulators ----
    uint32_t hacc[5][4][2];
    #pragma unroll
    for (int t = 0; t < 5; t++)
        #pragma unroll
        for (int n = 0; n < 4; n++) { hacc[t][n][0] = 0u; hacc[t][n][1] = 0u; }

    const int nrow = lane >> 2;
    const int kq   = lane & 3;
    const uint32_t bqbase = OB_B + h * BQ_B;

    for (int i = 0; i < NKC; i++) {
        __syncthreads();                          // prior reads of slot (i+3)&3 done
        if (tid == 0 && i + 3 < NKC) {
            int b = (i + 3) & 3;
            mbar_expect_tx(MB + b * 8, CHUNK_BYTES);
            bulk_ld(smb + OB_A + b * CHUNK_BYTES, g_Ah + (size_t)(i + 3) * CHUNK_BYTES,
                    CHUNK_BYTES, MB + b * 8);
        }
        mbar_wait(MB + (i & 3) * 8, (i >> 2) & 1);
        const uint32_t abase = smb + OB_A + (i & 3) * CHUNK_BYTES;

        uint32_t bf[4][2];
        #pragma unroll
        for (int nt = 0; nt < 3; nt++) {
            int n = nt * 8 + nrow;
            uint32_t bidx = bqbase + (uint32_t)(n * 648 + i * 16 + kq * 2) * 2;
            bf[nt][0] = *(const uint32_t*)(smraw + bidx);
            bf[nt][1] = *(const uint32_t*)(smraw + bidx + 16);
        }
        if (nrow == 0) {   // only n=24 valid in last n-tile
            uint32_t bidx = bqbase + (uint32_t)(24 * 648 + i * 16 + kq * 2) * 2;
            bf[3][0] = *(const uint32_t*)(smraw + bidx);
            bf[3][1] = *(const uint32_t*)(smraw + bidx + 16);
        } else {
            bf[3][0] = 0u; bf[3][1] = 0u;
        }

        #pragma unroll
        for (int j = 0; j < 5; j++) {
            int mt = wl + 8 * j;
            int m = mt * 16 + (lane & 15);
            uint32_t addr = abase + m * 32 + ((((lane >> 4) ^ (m >> 2)) & 1) << 4);
            uint32_t a0, a1, a2, a3;
            ldsm_x4(a0, a1, a2, a3, addr);
            #pragma unroll
            for (int nt = 0; nt < 4; nt++)
                mma16816h(hacc[j][nt][0], hacc[j][nt][1],
                          a0, a1, a2, a3, bf[nt][0], bf[nt][1]);
        }
    }
    __syncthreads();   // ring + B operands dead

    // prefetch raw fq0 for output into B region (overlaps epilogue)
    if (tid == 0) {
        mbar_expect_tx(MB + 6 * 8, TILE * 4);
        bulk_ld(smb + OB_B, ftest + (size_t)q0 * TILE, TILE * 4, MB + 6 * 8);
    }

    // ---- store G (already fp16 — raw 4B stores) ----
    {
        __half* gh = (__half*)(smraw + OB_A + h * GH_STRIDE);
        #pragma unroll
        for (int j = 0; j < 5; j++) {
            int mt = wl + 8 * j;
            int r0 = mt * 16 + (lane >> 2);
            int r1 = r0 + 8;
            #pragma unroll
            for (int nt = 0; nt < 4; nt++) {
                int c = nt * 8 + (lane & 3) * 2;
                if (c + 1 < 25) {
                    if (r0 < 625) *(uint32_t*)(gh + r0 * 26 + c) = hacc[j][nt][0];
                    if (r1 < 625) *(uint32_t*)(gh + r1 * 26 + c) = hacc[j][nt][1];
                } else if (c < 25) {
                    __half2 v0 = *reinterpret_cast<__half2*>(&hacc[j][nt][0]);
                    __half2 v1 = *reinterpret_cast<__half2*>(&hacc[j][nt][1]);
                    if (r0 < 625) gh[r0 * 26 + c] = __low2half(v0);
                    if (r1 < 625) gh[r1 * 26 + c] = __low2half(v1);
                }
            }
        }
    }
    asm volatile("bar.sync %0, 256;" :: "r"(h + 1) : "memory");

    // ---- per-p epilogue (halves parallel) ----
    {
        const __half* gh = (const __half*)(smraw + OB_A + h * GH_STRIDE);
        for (int p = wl; p < PP; p += 8) {
            float* kn = smf + KNI + w * 112;
            if (lane < 25) {
                float a1 = 0.f, a2 = 0.f;
                int rowb = (p * 25 + lane) * 26;
                int colb = p * 25 * 26 + lane;
                #pragma unroll
                for (int j = 0; j < 25; j++) {
                    a1 += __half2float(gh[rowb + j]);
                    a2 += __half2float(gh[colb + j * 26]);
                }
                kn[lane]      = a1 * (1.f / 25.f);   // g1
                kn[25 + lane] = a2 * (1.f / 25.f);   // g2
            }
            __syncwarp();
            if (lane < 5) {
                float a = smf[OB_B1F/4 + lane];
                #pragma unroll
                for (int j = 0; j < 25; j++) a += kn[j] * smf[OB_W1F/4 + lane * 25 + j];
                kn[50 + lane] = fmaxf(a, 0.f);
            } else if (lane >= 8 && lane < 13) {
                int ii = lane - 8;
                float a = smf[OB_B1F/4 + ii];
                #pragma unroll
                for (int j = 0; j < 25; j++) a += kn[25 + j] * smf[OB_W1F/4 + ii * 25 + j];
                kn[55 + ii] = fmaxf(a, 0.f);
            }
            __syncwarp();
            if (lane < 25) {
                float a1 = smf[OB_B2S/4 + lane], a2 = a1;
                #pragma unroll
                for (int ii = 0; ii < 5; ii++) {
                    float wv = smf[OB_W2/4 + lane * 5 + ii];
                    a1 += kn[50 + ii] * wv;
                    a2 += kn[55 + ii] * wv;
                }
                kn[60 + lane] = fmaxf(a1, 0.f);  // k1
                kn[85 + lane] = fmaxf(a2, 0.f);  // k2
            }
            __syncwarp();
            if (lane < 25) {
                float att1 = 0.f, attt = 0.f;
                int colb = p * 25 * 26 + lane;
                int rowb = (p * 25 + lane) * 26;
                #pragma unroll
                for (int j = 0; j < 25; j++) {
                    att1 += kn[60 + j] * __half2float(gh[colb + j * 26]);
                    attt += __half2float(gh[rowb + j]) * kn[85 + j];
                }
                smf[AT1I + h * AT1S + p * 25 + lane] = att1;
                smf[ATI + h * 625 + p * 25 + lane]   = attt;
            }
        }
    }
    __syncthreads();   // both halves done with G

    // prefetch raw fq1 for output into A region
    if (tid == 0) {
        mbar_expect_tx(MB + 7 * 8, TILE * 4);
        bulk_ld(smb + OB_A, ftest + (size_t)(q0 + 1) * TILE, TILE * 4, MB + 7 * 8);
    }

    // ---- softmaxes (per half) ----
    if (wl == 0) {
        float val = 0.f;
        if (lane < 25) {
            #pragma unroll
            for (int j = 0; j < 25; j++) val += smf[ATI + h * 625 + j * 25 + lane];
            val *= (1.f / 25.f);
        }
        float m = (lane < 25) ? val : -1e30f;
        #pragma unroll
        for (int o = 16; o; o >>= 1) m = fmaxf(m, __shfl_xor_sync(0xffffffffu, m, o));
        float e = (lane < 25) ? expf(val - m) : 0.f;
        float ssum = e;
        #pragma unroll
        for (int o = 16; o; o >>= 1) ssum += __shfl_xor_sync(0xffffffffu, ssum, o);
        float a = e / ssum;
        if (lane < 25) {
            out[OFT_AM + q * SS + lane] = a;
            smf[OB_TS/4 + h * 25 + lane] = a + 1.f;
        }
    } else if (wl == 1) {
        float rs = 0.f;
        if (lane < 25) {
            #pragma unroll
            for (int j = 0; j < 25; j++) rs += smf[ATI + h * 625 + lane * 25 + j];
        }
        int g = (lane < 5) ? lane : 4;
        float cg = 0.f;
        #pragma unroll
        for (int i = 0; i < 5; i++) cg += __shfl_sync(0xffffffffu, rs, g * 5 + i);
        cg *= (1.f / 125.f);
        float m = (lane < 5) ? cg : -1e30f;
        #pragma unroll
        for (int o = 4; o; o >>= 1) m = fmaxf(m, __shfl_xor_sync(0xffffffffu, m, o));
        float e = (lane < 5) ? expf(cg - m) : 0.f;
        float ssum = e;
        #pragma unroll
        for (int o = 4; o; o >>= 1) ssum += __shfl_xor_sync(0xffffffffu, ssum, o);
        if (lane < 5) out[OFT_CLS + q * 5 + lane] = e / ssum;
    }
    asm volatile("bar.sync %0, 256;" :: "r"(h + 1) : "memory");  // TS[h] ready

    // ---- output: half h scales its fq in smem, bulk-stores out + att1 ----
    {
        const uint32_t stage_off = (h == 0) ? OB_B : OB_A;
        mbar_wait(MB + (6 + h) * 8, 0);
        float4* st4 = (float4*)(smraw + stage_off);
        const int t2 = tid & 255;
        for (int i = t2; i < 4000; i += 256) {
            float4 b = st4[i];
            int s = (i * 4) % 25;
            b.x *= smf[OB_TS/4 + h * 25 + s]; s = (s == 24) ? 0 : s + 1;
            b.y *= smf[OB_TS/4 + h * 25 + s]; s = (s == 24) ? 0 : s + 1;
            b.z *= smf[OB_TS/4 + h * 25 + s]; s = (s == 24) ? 0 : s + 1;
            b.w *= smf[OB_TS/4 + h * 25 + s];
            st4[i] = b;
        }
        asm volatile("bar.sync %0, 256;" :: "r"(h + 1) : "memory");
        if (t2 == 0) {
            FENCE_ASYNC();
            bulk_st(out + OFT_TE + (size_t)q * TILE, smb + stage_off, TILE * 4);
            bulk_st(g_att1 + (size_t)q * AT1S, smb + OB_AT1 + h * (AT1S * 4), AT1S * 4);
            BULK_COMMIT();
            BULK_WAIT0();
        }
    }
    __syncthreads();   // keep smem alive until bulk stores complete
}

// ---------------- K3a: partial reduce of att1 over q slices ----------------
__global__ void __launch_bounds__(128) cam_final1() {
    __shared__ float red[125];
    int p = blockIdx.x >> 3, sl = blockIdx.x & 7;
    int tid = threadIdx.x;
    if (tid < 125) {
        int s = tid % 25, grp = tid / 25;
        const float* base = g_att1 + p * 25 + s;
        float acc = 0.f;
        for (int qq = sl * 250 + grp; qq < (sl + 1) * 250; qq += 5)
            acc += base[(size_t)qq * AT1S];
        red[tid] = acc;
    }
    __syncthreads();
    if (tid < 25) {
        float v = red[tid] + red[25 + tid] + red[50 + tid] + red[75 + tid] + red[100 + tid];
        g_part[blockIdx.x * 25 + tid] = v;
    }
}

// ---------------- K3b: combine, softmax, ftrain_out ----------------
__global__ void __launch_bounds__(256) cam_final2(const float* __restrict__ ftrain,
                                                  float* __restrict__ out) {
    __shared__ float att_s[SS];
    int p = blockIdx.x, tid = threadIdx.x, lane = tid & 31, w = tid >> 5;
    if (w == 0) {
        float val = 0.f;
        if (lane < 25) {
            #pragma unroll
            for (int k = 0; k < 8; k++) val += g_part[(p * 8 + k) * 25 + lane];
            val *= (1.f / (float)QQ);
        }
        float m = (lane < 25) ? val : -1e30f;
        #pragma unroll
        for (int o = 16; o; o >>= 1) m = fmaxf(m, __shfl_xor_sync(0xffffffffu, m, o));
        float e = (lane < 25) ? expf(val - m) : 0.f;
        float ssum = e;
        #pragma unroll
        for (int o = 16; o; o >>= 1) ssum += __shfl_xor_sync(0xffffffffu, ssum, o);
        if (lane < 25) att_s[lane] = e / ssum + 1.f;
    }
    __syncthreads();
    const float4* fp4 = (const float4*)(ftrain + p * TILE);
    float4* outp = (float4*)(out + (size_t)p * TILE);
    for (int i = tid; i < 4000; i += 256) {
        float4 b = fp4[i];
        int s = (i * 4) % 25;
        float4 o;
        o.x = b.x * att_s[s]; s = (s == 24) ? 0 : s + 1;
        o.y = b.y * att_s[s]; s = (s == 24) ? 0 : s + 1;
        o.z = b.z * att_s[s]; s = (s == 24) ? 0 : s + 1;
        o.w = b.w * att_s[s];
        outp[i] = o;
    }
}

// ---------------- launch ----------------
extern "C" void kernel_launch(void* const* d_in, const int* in_sizes, int n_in,
                              void* d_out, int out_size) {
    const float* ftrain  = (const float*)d_in[0];
    const float* ftest   = (const float*)d_in[1];
    const float* conv1_w = (const float*)d_in[6];
    const float* conv1_b = (const float*)d_in[7];
    const float* bn_gamma= (const float*)d_in[8];
    const float* bn_beta = (const float*)d_in[9];
    const float* bn_mean = (const float*)d_in[10];
    const float* bn_var  = (const float*)d_in[11];
    const float* conv2_w = (const float*)d_in[12];
    const float* conv2_b = (const float*)d_in[13];
    float* out = (float*)d_out;

    const int prepA_smem = 64128 + 32000;
    cudaFuncSetAttribute(cam_prep_A, cudaFuncAttributeMaxDynamicSharedMemorySize, prepA_smem);
    cudaFuncSetAttribute(cam_main,   cudaFuncAttributeMaxDynamicSharedMemorySize, SMEM_BYTES);

    cam_prep_A<<<PP, 256, prepA_smem>>>(ftrain);
    cam_main<<<QQ / 2, 512, SMEM_BYTES>>>(ftest, conv1_w, conv1_b, bn_gamma, bn_beta,
                                          bn_mean, bn_var, conv2_w, conv2_b, out);
    cam_final1<<<200, 128>>>();
    cam_final2<<<PP, 256>>>(ftrain, out);
}